// round 9
// baseline (speedup 1.0000x reference)
#include <cuda_runtime.h>
#include <cuda_bf16.h>
#include <cstdint>

// PCEN, 10 smoother coefficients.
//   m[s,t] = (1-s)*m[s,t-1] + s*x[t],  m[s,0] = x[0]
//   out = (x*(EPS+m)^(-alpha) + delta)^r - delta^r
//
// R9: R8 (RPT=8, CPW=2, 3 MUFU + 1 poly-ex2) with register-footprint trim:
// persistent chain state 11->7 regs (a16..a128 recomputed per chunk, ~0.03
// inst/elem), epilogue split into two 4-elem halves with store in between,
// __launch_bounds__(128,8) targeting 64 regs -> 32 warps/SM (50% occ).

#define PCEN_EPS 1e-5f
#define NS 10
#define CPW 2
#define NPAIR (NS / CPW)
#define TT 2048
#define RPT 8
#define CHUNK (32 * RPT)          // 256
#define NCHUNK (TT / CHUNK)       // 8

__device__ __forceinline__ float fast_ex2(float v) {
    float r; asm("ex2.approx.ftz.f32 %0, %1;" : "=f"(r) : "f"(v)); return r;
}
__device__ __forceinline__ float fast_lg2(float v) {
    float r; asm("lg2.approx.ftz.f32 %0, %1;" : "=f"(r) : "f"(v)); return r;
}

// 2^v on FMA/ALU pipes (no MUFU). Valid for |v| < ~126.
__device__ __forceinline__ float poly_ex2(float v) {
    const float magic = 12582912.0f;           // 1.5 * 2^23
    float fl = v + magic;                      // RN -> integer in low mantissa
    int   iv = __float_as_int(fl);
    float t  = v - (fl - magic);               // t in [-0.5, 0.5]
    float u  = t * 0.6931471805599453f;
    float p  = fmaf(u, 8.3333333e-3f, 4.1666667e-2f);
    p = fmaf(p, u, 0.16666667f);
    p = fmaf(p, u, 0.5f);
    p = fmaf(p, u, 1.0f);
    p = fmaf(p, u, 1.0f);
    return __int_as_float(__float_as_int(p) + (iv << 23));
}

__device__ __forceinline__ float pcen_elem(float xv, float m,
                                           float alpha, float delta,
                                           float r, float delta_r) {
    const float sm = fast_ex2(-alpha * fast_lg2(PCEN_EPS + m));
    return poly_ex2(r * fast_lg2(fmaf(xv, sm, delta))) - delta_r;
}

__global__ __launch_bounds__(128, 8) void pcen_kernel(
    const float* __restrict__ x,
    const float* __restrict__ s_log,
    const float* __restrict__ alpha_log,
    const float* __restrict__ delta_log,
    const float* __restrict__ r_log,
    float* __restrict__ out,
    int F, int BF)
{
    const int gwarp = (blockIdx.x * blockDim.x + threadIdx.x) >> 5;
    const int lane  = threadIdx.x & 31;
    if (gwarp >= BF * NPAIR) return;

    const int row  = gwarp / NPAIR;
    const int pair = gwarp % NPAIR;
    const int i0   = pair * CPW;

    const int b = row / F;
    const int f = row % F;

    const float alpha = __expf(alpha_log[f]);
    const float delta = __expf(delta_log[f]);
    const float r     = __expf(r_log[f]);
    const float delta_r = fast_ex2(r * fast_lg2(delta));

    const float4* __restrict__ xp4 = (const float4*)(x + (size_t)row * TT);
    float* __restrict__ op = out + (((size_t)b * NS + i0) * F + f) * (size_t)TT;
    const size_t s_stride = (size_t)F * TT;

    // persistent per-chain state: 7 regs per chain
    float sv[CPW], a1[CPW], a2[CPW], a4[CPW], a8[CPW];
    float a8lane[CPW], carry[CPW];

    const float x0 = ((const float*)xp4)[0];

    #pragma unroll
    for (int c = 0; c < CPW; c++) {
        const float s = __expf(s_log[i0 + c]);
        sv[c] = s;
        const float a = 1.0f - s;
        a1[c] = a;
        a2[c] = a * a;
        a4[c] = a2[c] * a2[c];
        a8[c] = a4[c] * a4[c];
        const float a16  = a8[c] * a8[c];
        const float a32  = a16 * a16;
        const float a64  = a32 * a32;
        const float a128 = a64 * a64;
        float ap = 1.0f;                        // (a^8)^lane
        if (lane & 1)  ap *= a8[c];
        if (lane & 2)  ap *= a16;
        if (lane & 4)  ap *= a32;
        if (lane & 8)  ap *= a64;
        if (lane & 16) ap *= a128;
        a8lane[c] = ap;
        carry[c] = x0;   // m_{-1} = x0 -> m_0 = x0 (reference init)
    }

    for (int ch = 0; ch < NCHUNK; ch++) {
        // lane owns t in [ch*256 + lane*8, +8): two float4 loads
        const int base4 = ch * 64 + lane * 2;
        const float4 xa = xp4[base4];
        const float4 xb = xp4[base4 + 1];

        #pragma unroll
        for (int c = 0; c < CPW; c++) {
            const float s = sv[c];
            const float a = a1[c];
            // local serial IIR (zero init), 8 steps
            const float l0 = s * xa.x;
            const float l1 = fmaf(a, l0, s * xa.y);
            const float l2 = fmaf(a, l1, s * xa.z);
            const float l3 = fmaf(a, l2, s * xa.w);
            const float l4 = fmaf(a, l3, s * xb.x);
            const float l5 = fmaf(a, l4, s * xb.y);
            const float l6 = fmaf(a, l5, s * xb.z);
            const float l7 = fmaf(a, l6, s * xb.w);

            // recompute scan powers (4 muls per chain per chunk - negligible)
            const float a16  = a8[c] * a8[c];
            const float a32  = a16 * a16;
            const float a64  = a32 * a32;
            const float a128 = a64 * a64;

            // Kogge-Stone over lane aggregates (ratio a^8)
            float S = l7;
            float v;
            v = __shfl_up_sync(0xFFFFFFFFu, S, 1);  if (lane >= 1)  S = fmaf(a8[c], v, S);
            v = __shfl_up_sync(0xFFFFFFFFu, S, 2);  if (lane >= 2)  S = fmaf(a16,   v, S);
            v = __shfl_up_sync(0xFFFFFFFFu, S, 4);  if (lane >= 4)  S = fmaf(a32,   v, S);
            v = __shfl_up_sync(0xFFFFFFFFu, S, 8);  if (lane >= 8)  S = fmaf(a64,   v, S);
            v = __shfl_up_sync(0xFFFFFFFFu, S, 16); if (lane >= 16) S = fmaf(a128,  v, S);

            const float P = __shfl_up_sync(0xFFFFFFFFu, S, 1);
            const float Mprev = (lane == 0) ? carry[c]
                                            : fmaf(a8lane[c], carry[c], P);
            const float S31 = __shfl_sync(0xFFFFFFFFu, S, 31);
            carry[c] = fmaf(a128 * a128, carry[c], S31);

            float* o = op + (size_t)c * s_stride + (size_t)ch * CHUNK + lane * RPT;

            // first half: m0..m3, compute + store
            {
                const float a3 = a1[c] * a2[c];
                const float m0 = fmaf(a1[c], Mprev, l0);
                const float m1 = fmaf(a2[c], Mprev, l1);
                const float m2 = fmaf(a3,    Mprev, l2);
                const float m3 = fmaf(a4[c], Mprev, l3);
                float4 oa;
                oa.x = pcen_elem(xa.x, m0, alpha, delta, r, delta_r);
                oa.y = pcen_elem(xa.y, m1, alpha, delta, r, delta_r);
                oa.z = pcen_elem(xa.z, m2, alpha, delta, r, delta_r);
                oa.w = pcen_elem(xa.w, m3, alpha, delta, r, delta_r);
                *(float4*)o = oa;
            }
            // second half: m4..m7, compute + store
            {
                const float a5 = a1[c] * a4[c];
                const float a6 = a2[c] * a4[c];
                const float a7 = a2[c] * a5;
                const float m4 = fmaf(a5,    Mprev, l4);
                const float m5 = fmaf(a6,    Mprev, l5);
                const float m6 = fmaf(a7,    Mprev, l6);
                const float m7 = fmaf(a8[c], Mprev, l7);
                float4 ob;
                ob.x = pcen_elem(xb.x, m4, alpha, delta, r, delta_r);
                ob.y = pcen_elem(xb.y, m5, alpha, delta, r, delta_r);
                ob.z = pcen_elem(xb.z, m6, alpha, delta, r, delta_r);
                ob.w = pcen_elem(xb.w, m7, alpha, delta, r, delta_r);
                *(float4*)(o + 4) = ob;
            }
        }
    }
}

extern "C" void kernel_launch(void* const* d_in, const int* in_sizes, int n_in,
                              void* d_out, int out_size)
{
    const float* x         = (const float*)d_in[0];
    const float* s_log     = (const float*)d_in[1];
    const float* alpha_log = (const float*)d_in[2];
    const float* delta_log = (const float*)d_in[3];
    const float* r_log     = (const float*)d_in[4];
    float* out = (float*)d_out;

    const int F  = in_sizes[2];
    const int BF = in_sizes[0] / TT;

    const int total_warps = BF * NPAIR;
    const int threads = 128;
    const int warps_per_block = threads / 32;
    const int blocks = (total_warps + warps_per_block - 1) / warps_per_block;

    pcen_kernel<<<blocks, threads>>>(x, s_log, alpha_log, delta_log, r_log,
                                     out, F, BF);
}